// round 16
// baseline (speedup 1.0000x reference)
#include <cuda_runtime.h>
#include <cuda_fp16.h>
#include <cstdint>

// Problem constants
#define BB 4
#define TT 2048
#define CC 1024
#define FF 4096
#define MROWS 8192

// ---------------------------------------------------------------------------
// PTX helpers (sm_103 base ISA: cp.async, ldmatrix, mma.sync)
// ---------------------------------------------------------------------------
__device__ __forceinline__ uint32_t smem_u32(const void* p) {
    uint32_t a;
    asm("{ .reg .u64 t; cvta.to.shared.u64 t, %1; cvt.u32.u64 %0, t; }" : "=r"(a) : "l"(p));
    return a;
}
__device__ __forceinline__ void cp_async16(uint32_t s, const void* g) {
    asm volatile("cp.async.cg.shared.global [%0], [%1], 16;" :: "r"(s), "l"(g) : "memory");
}
#define CP_COMMIT() asm volatile("cp.async.commit_group;" ::: "memory")
#define CP_WAIT(n)  asm volatile("cp.async.wait_group %0;" :: "n"(n) : "memory")

__device__ __forceinline__ void ldsm_x4(uint32_t* r, uint32_t addr) {
    asm volatile("ldmatrix.sync.aligned.m8n8.x4.shared.b16 {%0,%1,%2,%3}, [%4];"
                 : "=r"(r[0]), "=r"(r[1]), "=r"(r[2]), "=r"(r[3]) : "r"(addr));
}
__device__ __forceinline__ void ldsm_x4_t(uint32_t* r, uint32_t addr) {
    asm volatile("ldmatrix.sync.aligned.m8n8.x4.trans.shared.b16 {%0,%1,%2,%3}, [%4];"
                 : "=r"(r[0]), "=r"(r[1]), "=r"(r[2]), "=r"(r[3]) : "r"(addr));
}
__device__ __forceinline__ void mma_f16(float* c, const uint32_t* a, const uint32_t* b) {
    asm volatile(
        "mma.sync.aligned.m16n8k16.row.col.f32.f16.f16.f32 "
        "{%0,%1,%2,%3}, {%4,%5,%6,%7}, {%8,%9}, {%0,%1,%2,%3};"
        : "+f"(c[0]), "+f"(c[1]), "+f"(c[2]), "+f"(c[3])
        : "r"(a[0]), "r"(a[1]), "r"(a[2]), "r"(a[3]), "r"(b[0]), "r"(b[1]));
}
__device__ __forceinline__ uint32_t pack_h2(float a, float b) {
    __half2 h = __floats2half2_rn(a, b);
    return reinterpret_cast<uint32_t&>(h);
}
__device__ __forceinline__ float fast_exp2(float x) {
    float y;
    asm("ex2.approx.f32 %0, %1;" : "=f"(y) : "f"(x));
    return y;
}

// ---------------------------------------------------------------------------
// Scratch (device globals)
// ---------------------------------------------------------------------------
__device__ __half g_xh[MROWS * CC];
__device__ __half g_Bqkv[3072 * CC];
__device__ __half g_Bp[CC * CC], g_B1[FF * CC], g_B2[CC * FF];
__device__ __half g_qkv[MROWS * 3072];
__device__ __half g_yh[MROWS * CC];
__device__ __half g_x2h[MROWS * CC];
__device__ __half g_h1h[MROWS * FF];

// ---------------------------------------------------------------------------
// Fused prepass: ONE launch (identical to R12-R15).
// ---------------------------------------------------------------------------
__global__ __launch_bounds__(256) void prepass_all(
    const float* __restrict__ x, __half* __restrict__ xh,
    const float* __restrict__ Wq, const float* __restrict__ Wk,
    const float* __restrict__ Wv, const float* __restrict__ Wproj,
    const float* __restrict__ W1, const float* __restrict__ W2,
    __half* __restrict__ Bqkv, __half* __restrict__ Bp,
    __half* __restrict__ B1, __half* __restrict__ B2)
{
    const int bid = blockIdx.x;
    if (bid < 12288) {
        __shared__ float t[32][33];
        const float* in; __half* out;
        int Cc, outK, nx, l;
        long inBatch, off;
        bool qkv3 = false;
        if (bid < 3072) {
            int which = bid >> 10; l = bid & 1023;
            in = (which == 0) ? Wq : (which == 1) ? Wk : Wv;
            out = Bqkv; Cc = 64; inBatch = (long)CC * 64;
            off = (long)which * 1024; outK = CC; nx = 2; qkv3 = true;
        } else if (bid < 4096) {
            l = bid - 3072; in = Wproj; out = Bp;
            Cc = CC; inBatch = 0; off = 0; outK = CC; nx = 32;
        } else if (bid < 8192) {
            l = bid - 4096; in = W1; out = B1;
            Cc = FF; inBatch = 0; off = 0; outK = CC; nx = 128;
        } else {
            l = bid - 8192; in = W2; out = B2;
            Cc = CC; inBatch = 0; off = 0; outK = FF; nx = 32;
        }
        int xb = l % nx, rest = l / nx;
        int yb = qkv3 ? (rest % 32) : rest;
        int zb = qkv3 ? (rest / 32) : 0;
        int r0 = yb * 32, c0 = xb * 32;
        int tx = threadIdx.x & 31, ty = threadIdx.x >> 5;
#pragma unroll
        for (int j = 0; j < 4; j++) {
            int r = r0 + ty + j * 8;
            t[ty + j * 8][tx] = in[(size_t)zb * inBatch + (size_t)r * Cc + c0 + tx];
        }
        __syncthreads();
#pragma unroll
        for (int j = 0; j < 4; j++) {
            int cI = c0 + ty + j * 8;
            size_t orow = (size_t)off + (size_t)zb * Cc + cI;
            out[orow * outK + r0 + tx] = __float2half_rn(t[tx][ty + j * 8]);
        }
    } else {
        int i = (bid - 12288) * 256 + threadIdx.x;
        float4 v = reinterpret_cast<const float4*>(x)[i];
        __half2 hA = __floats2half2_rn(v.x, v.y);
        __half2 hB = __floats2half2_rn(v.z, v.w);
        reinterpret_cast<__half2*>(xh)[i * 2]     = hA;
        reinterpret_cast<__half2*>(xh)[i * 2 + 1] = hB;
    }
}

// ---------------------------------------------------------------------------
// fp16 GEMM: C[M,N] = A[M,K] * B[N,K]^T.  Structure = R15 (frozen).
// NEW: whole-chunk fragment preload — 12 ldsm issued before all 32 MMAs,
// hiding ldsm latency behind the MMA run. Pinned 2 CTAs/SM (<=128 regs).
// ---------------------------------------------------------------------------
#define TILE_B   (128 * 80)
#define CHUNK_B  (2 * TILE_B)
#define NSTAGE   4
#define GEMM_SMEM (NSTAGE * CHUNK_B)

template <bool BIAS, bool RELU, bool RES, bool RESH, bool OUTF, bool OUTH>
__global__ __launch_bounds__(256, 2) void gemm_mma(
    const __half* __restrict__ A_, const __half* __restrict__ B_,
    const float* __restrict__ bias, const float* __restrict__ res,
    const __half* __restrict__ resh,
    float* __restrict__ Cf, __half* __restrict__ Ch,
    int M, int N, int K)
{
    extern __shared__ char smem[];
    const uint32_t sb = smem_u32(smem);
    const int tid = threadIdx.x;
    const int lane = tid & 31, wid = tid >> 5;
    const int rowBase = blockIdx.y * 128;
    const int colBase = blockIdx.x * 128;
    const int lr = tid >> 2, ls = tid & 3;

    auto issue = [&](int c) {
        const int k0 = c << 5;
        const uint32_t buf = sb + (uint32_t)(c % NSTAGE) * CHUNK_B;
#pragma unroll
        for (int i = 0; i < 2; i++) {
            int r = lr + i * 64;
            uint32_t so = (uint32_t)r * 80 + ls * 16;
            size_t gA = (size_t)(rowBase + r) * K + k0 + ls * 8;
            size_t gB = (size_t)(colBase + r) * K + k0 + ls * 8;
            cp_async16(buf + so,          A_ + gA);
            cp_async16(buf + TILE_B + so, B_ + gB);
        }
        CP_COMMIT();
    };

    const int wm = wid >> 2, wn = wid & 3;
    const int t8 = lane >> 3, r8 = lane & 7;
    const int aR = r8 + ((t8 & 1) << 3);
    const int aK = (t8 & 2) << 2;
    const int bR = r8 + ((t8 >> 1) << 3);
    const int bK = (t8 & 1) << 3;

    float acc[4][4][4];
#pragma unroll
    for (int i = 0; i < 4; i++)
#pragma unroll
        for (int j = 0; j < 4; j++)
#pragma unroll
            for (int q = 0; q < 4; q++) acc[i][j][q] = 0.0f;

    const int nch = K >> 5;
    issue(0); issue(1); issue(2);

    for (int c = 0; c < nch; c++) {
        const int rem = nch - 1 - c;
        if (rem >= 2)      { CP_WAIT(2); }
        else if (rem == 1) { CP_WAIT(1); }
        else               { CP_WAIT(0); }
        __syncthreads();
        if (c + 3 < nch) issue(c + 3);

        const uint32_t buf = sb + (uint32_t)(c % NSTAGE) * CHUNK_B;
        const uint32_t aB = buf + (uint32_t)(wm * 64 + aR) * 80 + aK * 2;
        const uint32_t bB = buf + TILE_B + (uint32_t)(wn * 32 + bR) * 80 + bK * 2;

        // Whole-chunk fragment preload: 12 ldsm first, then 32 MMAs.
        uint32_t ah[2][4][4], bb[2][2][4];
#pragma unroll
        for (int ks = 0; ks < 2; ks++) {
            const uint32_t ko = ks * 32;
#pragma unroll
            for (int mt = 0; mt < 4; mt++)
                ldsm_x4(ah[ks][mt], aB + (uint32_t)mt * 16 * 80 + ko);
#pragma unroll
            for (int j = 0; j < 2; j++)
                ldsm_x4(bb[ks][j], bB + (uint32_t)j * 16 * 80 + ko);
        }
#pragma unroll
        for (int ks = 0; ks < 2; ks++) {
#pragma unroll
            for (int mt = 0; mt < 4; mt++) {
#pragma unroll
                for (int nt = 0; nt < 4; nt++)
                    mma_f16(acc[mt][nt], ah[ks][mt], &bb[ks][nt >> 1][(nt & 1) * 2]);
            }
        }
    }

    const int lrr = lane >> 2, lcc = (lane & 3) * 2;
#pragma unroll
    for (int mt = 0; mt < 4; mt++) {
#pragma unroll
        for (int half = 0; half < 2; half++) {
            const int row = rowBase + wm * 64 + mt * 16 + lrr + half * 8;
#pragma unroll
            for (int nt = 0; nt < 4; nt++) {
                const int col = colBase + wn * 32 + nt * 8 + lcc;
                float v0 = acc[mt][nt][half * 2];
                float v1 = acc[mt][nt][half * 2 + 1];
                if (BIAS) { v0 += bias[col]; v1 += bias[col + 1]; }
                if (RES) {
                    const float2 r2 = *reinterpret_cast<const float2*>(
                        &res[(size_t)row * N + col]);
                    v0 += r2.x; v1 += r2.y;
                }
                if (RESH) {
                    const __half2 rh = *reinterpret_cast<const __half2*>(
                        &resh[(size_t)row * N + col]);
                    v0 += __half2float(rh.x); v1 += __half2float(rh.y);
                }
                if (RELU) { v0 = fmaxf(v0, 0.f); v1 = fmaxf(v1, 0.f); }
                const size_t o = (size_t)row * N + col;
                if (OUTF) {
                    float2 w = {v0, v1};
                    *reinterpret_cast<float2*>(&Cf[o]) = w;
                }
                if (OUTH)
                    *reinterpret_cast<__half2*>(&Ch[o]) = __floats2half2_rn(v0, v1);
            }
        }
    }
}

// ---------------------------------------------------------------------------
// fp16 mma flash attention, causal (R13 body, LPT dispatch). Unchanged.
// ---------------------------------------------------------------------------
#define AQH 0
#define AKVB 18432
#define ATTN_SMEM (18432 + 3 * 18432)   // 73728

__global__ __launch_bounds__(256) void attn_mma(
    const __half* __restrict__ qkv, __half* __restrict__ yh)
{
    extern __shared__ char smem[];
    const uint32_t sb = smem_u32(smem);
    const int tid = threadIdx.x, lane = tid & 31, w = tid >> 5;
    const int bhh = blockIdx.y, b = bhh >> 4, h = bhh & 15;
    const int xi = gridDim.x - 1 - blockIdx.x;   // LPT: heavy CTAs first
    const int t0 = xi * 128;
    const int last = 2 * xi + 1;                 // >= 1 always
    const size_t rbase = ((size_t)b * TT) * 3072 + h * 64;
    const float SC2 = 0.045084220027780106f;     // scale * log2(e)

    // Q load: group 0
    {
        const int qr = tid >> 1;
        const int sg = (tid & 1) * 4;
#pragma unroll
        for (int j = 0; j < 4; j++) {
            size_t g = rbase + (size_t)(t0 + qr) * 3072 + (sg + j) * 8;
            uint32_t so = (uint32_t)qr * 144 + (sg + j) * 16;
            cp_async16(sb + AQH + so, qkv + g);
        }
    }
    CP_COMMIT();

    const int kr = tid >> 2;
    const int ksg = (tid & 3) * 2;
    auto issueKV = [&](int it) {
        const int s0 = it * 64;
        const uint32_t pb = AKVB + (uint32_t)(it % 3) * 18432;
#pragma unroll
        for (int j = 0; j < 2; j++) {
            size_t gk = rbase + 1024 + (size_t)(s0 + kr) * 3072 + (ksg + j) * 8;
            uint32_t so = (uint32_t)kr * 144 + (ksg + j) * 16;
            cp_async16(sb + pb + so, qkv + gk);               // K
            cp_async16(sb + pb + 9216 + so, qkv + gk + 1024); // V
        }
        CP_COMMIT();
    };

    issueKV(0);
    issueKV(1);
    CP_WAIT(2);
    __syncthreads();

    const int t8 = lane >> 3, r8 = lane & 7;
    const int aR = r8 + ((t8 & 1) << 3);
    const int aK = (t8 & 2) << 2;
    const int bR = r8 + ((t8 >> 1) << 3);
    const int bK = (t8 & 1) << 3;

    uint32_t qf[4][4];
#pragma unroll
    for (int kd = 0; kd < 4; kd++)
        ldsm_x4(qf[kd], sb + AQH + (uint32_t)(w * 16 + aR) * 144 + (kd * 16 + aK) * 2);

    float m[2] = {-1e30f, -1e30f}, l[2] = {0.f, 0.f};
    float O[8][4];
#pragma unroll
    for (int i = 0; i < 8; i++)
#pragma unroll
        for (int j = 0; j < 4; j++) O[i][j] = 0.f;

    const int qr0 = w * 16 + (lane >> 2);

    for (int it = 0; it <= last; it++) {
        if (it < last) { CP_WAIT(1); } else { CP_WAIT(0); }
        __syncthreads();
        if (it + 2 <= last) issueKV(it + 2);

        const uint32_t pb = AKVB + (uint32_t)(it % 3) * 18432;
        const int s0 = it * 64;

        float s[8][4];
#pragma unroll
        for (int i = 0; i < 8; i++)
#pragma unroll
            for (int j = 0; j < 4; j++) s[i][j] = 0.f;

#pragma unroll
        for (int kd = 0; kd < 4; kd++) {
            uint32_t kb[4][4];
#pragma unroll
            for (int g = 0; g < 4; g++)
                ldsm_x4(kb[g], sb + pb +
                        (uint32_t)(g * 16 + bR) * 144 + (kd * 16 + bK) * 2);
#pragma unroll
            for (int g = 0; g < 4; g++) {
                mma_f16(s[2 * g],     qf[kd], &kb[g][0]);
                mma_f16(s[2 * g + 1], qf[kd], &kb[g][2]);
            }
        }

#pragma unroll
        for (int nt = 0; nt < 8; nt++)
#pragma unroll
            for (int e = 0; e < 4; e++) s[nt][e] *= SC2;
        if (it >= last - 1) {
#pragma unroll
            for (int nt = 0; nt < 8; nt++)
#pragma unroll
                for (int e = 0; e < 4; e++) {
                    int kc = s0 + nt * 8 + (lane & 3) * 2 + (e & 1);
                    int qr = t0 + qr0 + (e >> 1) * 8;
                    if (kc > qr) s[nt][e] = -1e30f;
                }
        }

        float mn[2] = {m[0], m[1]};
#pragma unroll
        for (int nt = 0; nt < 8; nt++) {
            mn[0] = fmaxf(mn[0], fmaxf(s[nt][0], s[nt][1]));
            mn[1] = fmaxf(mn[1], fmaxf(s[nt][2], s[nt][3]));
        }
#pragma unroll
        for (int i = 0; i < 2; i++) {
            mn[i] = fmaxf(mn[i], __shfl_xor_sync(0xffffffffu, mn[i], 1));
            mn[i] = fmaxf(mn[i], __shfl_xor_sync(0xffffffffu, mn[i], 2));
        }
        float alpha[2];
#pragma unroll
        for (int i = 0; i < 2; i++) {
            alpha[i] = fast_exp2(m[i] - mn[i]);
            m[i] = mn[i];
        }
        float rs[2] = {0.f, 0.f};
#pragma unroll
        for (int nt = 0; nt < 8; nt++) {
#pragma unroll
            for (int e = 0; e < 4; e++) {
                float p = fast_exp2(s[nt][e] - m[e >> 1]);
                s[nt][e] = p;
                rs[e >> 1] += p;
            }
        }
#pragma unroll
        for (int i = 0; i < 2; i++) {
            rs[i] += __shfl_xor_sync(0xffffffffu, rs[i], 1);
            rs[i] += __shfl_xor_sync(0xffffffffu, rs[i], 2);
            l[i] = l[i] * alpha[i] + rs[i];
        }
#pragma unroll
        for (int nt = 0; nt < 8; nt++) {
            O[nt][0] *= alpha[0]; O[nt][1] *= alpha[0];
            O[nt][2] *= alpha[1]; O[nt][3] *= alpha[1];
        }

#pragma unroll
        for (int kk = 0; kk < 4; kk++) {
            uint32_t pa[4];
            pa[0] = pack_h2(s[2 * kk][0],     s[2 * kk][1]);
            pa[1] = pack_h2(s[2 * kk][2],     s[2 * kk][3]);
            pa[2] = pack_h2(s[2 * kk + 1][0], s[2 * kk + 1][1]);
            pa[3] = pack_h2(s[2 * kk + 1][2], s[2 * kk + 1][3]);
#pragma unroll
            for (int dg = 0; dg < 4; dg++) {
                uint32_t vb[4];
                ldsm_x4_t(vb, sb + pb + 9216 +
                          (uint32_t)(kk * 16 + aR) * 144 + (dg * 16 + aK) * 2);
                mma_f16(O[dg * 2],     pa, &vb[0]);
                mma_f16(O[dg * 2 + 1], pa, &vb[2]);
            }
        }
    }

    float inv[2] = {1.0f / l[0], 1.0f / l[1]};
    const size_t ob = ((size_t)b * TT) * CC + h * 64;
#pragma unroll
    for (int nt = 0; nt < 8; nt++) {
        int col = nt * 8 + (lane & 3) * 2;
#pragma unroll
        for (int i = 0; i < 2; i++) {
            int row = t0 + qr0 + i * 8;
            size_t o = ob + (size_t)row * CC + col;
            *reinterpret_cast<__half2*>(&yh[o]) =
                __floats2half2_rn(O[nt][2 * i] * inv[i], O[nt][2 * i + 1] * inv[i]);
        }
    }
}

// ---------------------------------------------------------------------------
// Launch sequence
// ---------------------------------------------------------------------------
extern "C" void kernel_launch(void* const* d_in, const int* in_sizes, int n_in,
                              void* d_out, int out_size)
{
    const float* x     = (const float*)d_in[0];
    const float* Wq    = (const float*)d_in[1];
    const float* Wk    = (const float*)d_in[2];
    const float* Wv    = (const float*)d_in[3];
    const float* Wproj = (const float*)d_in[4];
    const float* bproj = (const float*)d_in[5];
    const float* W1    = (const float*)d_in[6];
    const float* b1    = (const float*)d_in[7];
    const float* W2    = (const float*)d_in[8];
    const float* b2    = (const float*)d_in[9];
    float* out = (float*)d_out;

    __half *xh, *Bqkv, *Bp, *B1, *B2, *qkv, *yh, *x2h, *h1h;
    cudaGetSymbolAddress((void**)&xh,  g_xh);
    cudaGetSymbolAddress((void**)&Bqkv, g_Bqkv);
    cudaGetSymbolAddress((void**)&Bp,  g_Bp);
    cudaGetSymbolAddress((void**)&B1,  g_B1);   cudaGetSymbolAddress((void**)&B2, g_B2);
    cudaGetSymbolAddress((void**)&qkv, g_qkv);
    cudaGetSymbolAddress((void**)&yh,  g_yh);
    cudaGetSymbolAddress((void**)&x2h, g_x2h);
    cudaGetSymbolAddress((void**)&h1h, g_h1h);

    cudaFuncSetAttribute(gemm_mma<false,false,false,false,false,true>,
                         cudaFuncAttributeMaxDynamicSharedMemorySize, GEMM_SMEM);
    cudaFuncSetAttribute(gemm_mma<true,false,true,false,false,true>,
                         cudaFuncAttributeMaxDynamicSharedMemorySize, GEMM_SMEM);
    cudaFuncSetAttribute(gemm_mma<true,true,false,false,false,true>,
                         cudaFuncAttributeMaxDynamicSharedMemorySize, GEMM_SMEM);
    cudaFuncSetAttribute(gemm_mma<true,false,false,true,true,false>,
                         cudaFuncAttributeMaxDynamicSharedMemorySize, GEMM_SMEM);
    cudaFuncSetAttribute(attn_mma,
                         cudaFuncAttributeMaxDynamicSharedMemorySize, ATTN_SMEM);

    dim3 tpb(256);

    // Fused prepass
    prepass_all<<<20480, tpb>>>(x, xh, Wq, Wk, Wv, Wproj, W1, W2,
                                Bqkv, Bp, B1, B2);

    // Fused QKV -> qkv fp16
    gemm_mma<false,false,false,false,false,true>
        <<<dim3(3072 / 128, MROWS / 128), tpb, GEMM_SMEM>>>(
        xh, Bqkv, nullptr, nullptr, nullptr, nullptr, qkv, MROWS, 3072, CC);

    // Causal attention -> y fp16 (LPT order)
    attn_mma<<<dim3(TT / 128, BB * 16), tpb, ATTN_SMEM>>>(qkv, yh);

    // Output projection + bias + residual(x fp32) -> x2h fp16
    gemm_mma<true,false,true,false,false,true>
        <<<dim3(CC / 128, MROWS / 128), tpb, GEMM_SMEM>>>(
        yh, Bp, bproj, x, nullptr, nullptr, x2h, MROWS, CC, CC);

    // FF1: relu(x2 @ W1 + b1) -> h1 fp16
    gemm_mma<true,true,false,false,false,true>
        <<<dim3(FF / 128, MROWS / 128), tpb, GEMM_SMEM>>>(
        x2h, B1, b1, nullptr, nullptr, nullptr, h1h, MROWS, FF, CC);

    // FF2: h1 @ W2 + b2 + x2h (fp16 residual) -> out fp32
    gemm_mma<true,false,false,true,true,false>
        <<<dim3(CC / 128, MROWS / 128), tpb, GEMM_SMEM>>>(
        h1h, B2, b2, nullptr, x2h, out, nullptr, MROWS, CC, FF);
}

// round 17
// speedup vs baseline: 1.0140x; 1.0140x over previous
#include <cuda_runtime.h>
#include <cuda_fp16.h>
#include <cstdint>

// Problem constants
#define BB 4
#define TT 2048
#define CC 1024
#define FF 4096
#define MROWS 8192

// ---------------------------------------------------------------------------
// PTX helpers (sm_103 base ISA: cp.async, ldmatrix, mma.sync)
// ---------------------------------------------------------------------------
__device__ __forceinline__ uint32_t smem_u32(const void* p) {
    uint32_t a;
    asm("{ .reg .u64 t; cvta.to.shared.u64 t, %1; cvt.u32.u64 %0, t; }" : "=r"(a) : "l"(p));
    return a;
}
__device__ __forceinline__ void cp_async16(uint32_t s, const void* g) {
    asm volatile("cp.async.cg.shared.global [%0], [%1], 16;" :: "r"(s), "l"(g) : "memory");
}
#define CP_COMMIT() asm volatile("cp.async.commit_group;" ::: "memory")
#define CP_WAIT(n)  asm volatile("cp.async.wait_group %0;" :: "n"(n) : "memory")

__device__ __forceinline__ void ldsm_x4(uint32_t* r, uint32_t addr) {
    asm volatile("ldmatrix.sync.aligned.m8n8.x4.shared.b16 {%0,%1,%2,%3}, [%4];"
                 : "=r"(r[0]), "=r"(r[1]), "=r"(r[2]), "=r"(r[3]) : "r"(addr));
}
__device__ __forceinline__ void ldsm_x4_t(uint32_t* r, uint32_t addr) {
    asm volatile("ldmatrix.sync.aligned.m8n8.x4.trans.shared.b16 {%0,%1,%2,%3}, [%4];"
                 : "=r"(r[0]), "=r"(r[1]), "=r"(r[2]), "=r"(r[3]) : "r"(addr));
}
__device__ __forceinline__ void mma_f16(float* c, const uint32_t* a, const uint32_t* b) {
    asm volatile(
        "mma.sync.aligned.m16n8k16.row.col.f32.f16.f16.f32 "
        "{%0,%1,%2,%3}, {%4,%5,%6,%7}, {%8,%9}, {%0,%1,%2,%3};"
        : "+f"(c[0]), "+f"(c[1]), "+f"(c[2]), "+f"(c[3])
        : "r"(a[0]), "r"(a[1]), "r"(a[2]), "r"(a[3]), "r"(b[0]), "r"(b[1]));
}
__device__ __forceinline__ uint32_t pack_h2(float a, float b) {
    __half2 h = __floats2half2_rn(a, b);
    return reinterpret_cast<uint32_t&>(h);
}
__device__ __forceinline__ float fast_exp2(float x) {
    float y;
    asm("ex2.approx.f32 %0, %1;" : "=f"(y) : "f"(x));
    return y;
}

// ---------------------------------------------------------------------------
// Scratch (device globals)
// ---------------------------------------------------------------------------
__device__ __half g_xh[MROWS * CC];
__device__ __half g_Bqkv[3072 * CC];
__device__ __half g_Bp[CC * CC], g_B1[FF * CC], g_B2[CC * FF];
__device__ __half g_qkv[MROWS * 3072];
__device__ __half g_yh[MROWS * CC];
__device__ __half g_x2h[MROWS * CC];
__device__ __half g_h1h[MROWS * FF];

// ---------------------------------------------------------------------------
// Fused prepass: ONE launch (identical to R12-R15).
// ---------------------------------------------------------------------------
__global__ __launch_bounds__(256) void prepass_all(
    const float* __restrict__ x, __half* __restrict__ xh,
    const float* __restrict__ Wq, const float* __restrict__ Wk,
    const float* __restrict__ Wv, const float* __restrict__ Wproj,
    const float* __restrict__ W1, const float* __restrict__ W2,
    __half* __restrict__ Bqkv, __half* __restrict__ Bp,
    __half* __restrict__ B1, __half* __restrict__ B2)
{
    const int bid = blockIdx.x;
    if (bid < 12288) {
        __shared__ float t[32][33];
        const float* in; __half* out;
        int Cc, outK, nx, l;
        long inBatch, off;
        bool qkv3 = false;
        if (bid < 3072) {
            int which = bid >> 10; l = bid & 1023;
            in = (which == 0) ? Wq : (which == 1) ? Wk : Wv;
            out = Bqkv; Cc = 64; inBatch = (long)CC * 64;
            off = (long)which * 1024; outK = CC; nx = 2; qkv3 = true;
        } else if (bid < 4096) {
            l = bid - 3072; in = Wproj; out = Bp;
            Cc = CC; inBatch = 0; off = 0; outK = CC; nx = 32;
        } else if (bid < 8192) {
            l = bid - 4096; in = W1; out = B1;
            Cc = FF; inBatch = 0; off = 0; outK = CC; nx = 128;
        } else {
            l = bid - 8192; in = W2; out = B2;
            Cc = CC; inBatch = 0; off = 0; outK = FF; nx = 32;
        }
        int xb = l % nx, rest = l / nx;
        int yb = qkv3 ? (rest % 32) : rest;
        int zb = qkv3 ? (rest / 32) : 0;
        int r0 = yb * 32, c0 = xb * 32;
        int tx = threadIdx.x & 31, ty = threadIdx.x >> 5;
#pragma unroll
        for (int j = 0; j < 4; j++) {
            int r = r0 + ty + j * 8;
            t[ty + j * 8][tx] = in[(size_t)zb * inBatch + (size_t)r * Cc + c0 + tx];
        }
        __syncthreads();
#pragma unroll
        for (int j = 0; j < 4; j++) {
            int cI = c0 + ty + j * 8;
            size_t orow = (size_t)off + (size_t)zb * Cc + cI;
            out[orow * outK + r0 + tx] = __float2half_rn(t[tx][ty + j * 8]);
        }
    } else {
        int i = (bid - 12288) * 256 + threadIdx.x;
        float4 v = reinterpret_cast<const float4*>(x)[i];
        __half2 hA = __floats2half2_rn(v.x, v.y);
        __half2 hB = __floats2half2_rn(v.z, v.w);
        reinterpret_cast<__half2*>(xh)[i * 2]     = hA;
        reinterpret_cast<__half2*>(xh)[i * 2 + 1] = hB;
    }
}

// ---------------------------------------------------------------------------
// fp16 GEMM: C[M,N] = A[M,K] * B[N,K]^T.  EXACT R15 config (best known):
// CTA 128x128, warp tile 64x32, K-chunk 32, 4-stage cp.async, interleaved
// ldsm/MMA half-steps, pinned 2 CTAs/SM.
// ---------------------------------------------------------------------------
#define TILE_B   (128 * 80)
#define CHUNK_B  (2 * TILE_B)
#define NSTAGE   4
#define GEMM_SMEM (NSTAGE * CHUNK_B)

template <bool BIAS, bool RELU, bool RES, bool RESH, bool OUTF, bool OUTH>
__global__ __launch_bounds__(256, 2) void gemm_mma(
    const __half* __restrict__ A_, const __half* __restrict__ B_,
    const float* __restrict__ bias, const float* __restrict__ res,
    const __half* __restrict__ resh,
    float* __restrict__ Cf, __half* __restrict__ Ch,
    int M, int N, int K)
{
    extern __shared__ char smem[];
    const uint32_t sb = smem_u32(smem);
    const int tid = threadIdx.x;
    const int lane = tid & 31, wid = tid >> 5;
    const int rowBase = blockIdx.y * 128;
    const int colBase = blockIdx.x * 128;
    const int lr = tid >> 2, ls = tid & 3;

    auto issue = [&](int c) {
        const int k0 = c << 5;
        const uint32_t buf = sb + (uint32_t)(c % NSTAGE) * CHUNK_B;
#pragma unroll
        for (int i = 0; i < 2; i++) {
            int r = lr + i * 64;
            uint32_t so = (uint32_t)r * 80 + ls * 16;
            size_t gA = (size_t)(rowBase + r) * K + k0 + ls * 8;
            size_t gB = (size_t)(colBase + r) * K + k0 + ls * 8;
            cp_async16(buf + so,          A_ + gA);
            cp_async16(buf + TILE_B + so, B_ + gB);
        }
        CP_COMMIT();
    };

    const int wm = wid >> 2, wn = wid & 3;
    const int t8 = lane >> 3, r8 = lane & 7;
    const int aR = r8 + ((t8 & 1) << 3);
    const int aK = (t8 & 2) << 2;
    const int bR = r8 + ((t8 >> 1) << 3);
    const int bK = (t8 & 1) << 3;

    float acc[4][4][4];
#pragma unroll
    for (int i = 0; i < 4; i++)
#pragma unroll
        for (int j = 0; j < 4; j++)
#pragma unroll
            for (int q = 0; q < 4; q++) acc[i][j][q] = 0.0f;

    const int nch = K >> 5;
    issue(0); issue(1); issue(2);

    for (int c = 0; c < nch; c++) {
        const int rem = nch - 1 - c;
        if (rem >= 2)      { CP_WAIT(2); }
        else if (rem == 1) { CP_WAIT(1); }
        else               { CP_WAIT(0); }
        __syncthreads();
        if (c + 3 < nch) issue(c + 3);

        const uint32_t buf = sb + (uint32_t)(c % NSTAGE) * CHUNK_B;
        const uint32_t aB = buf + (uint32_t)(wm * 64 + aR) * 80 + aK * 2;
        const uint32_t bB = buf + TILE_B + (uint32_t)(wn * 32 + bR) * 80 + bK * 2;

#pragma unroll
        for (int ks = 0; ks < 2; ks++) {
            const uint32_t ko = ks * 32;
            uint32_t ah[4][4], bb[2][4];
#pragma unroll
            for (int mt = 0; mt < 4; mt++)
                ldsm_x4(ah[mt], aB + (uint32_t)mt * 16 * 80 + ko);
#pragma unroll
            for (int j = 0; j < 2; j++)
                ldsm_x4(bb[j], bB + (uint32_t)j * 16 * 80 + ko);
#pragma unroll
            for (int mt = 0; mt < 4; mt++) {
#pragma unroll
                for (int nt = 0; nt < 4; nt++)
                    mma_f16(acc[mt][nt], ah[mt], &bb[nt >> 1][(nt & 1) * 2]);
            }
        }
    }

    const int lrr = lane >> 2, lcc = (lane & 3) * 2;
#pragma unroll
    for (int mt = 0; mt < 4; mt++) {
#pragma unroll
        for (int half = 0; half < 2; half++) {
            const int row = rowBase + wm * 64 + mt * 16 + lrr + half * 8;
#pragma unroll
            for (int nt = 0; nt < 4; nt++) {
                const int col = colBase + wn * 32 + nt * 8 + lcc;
                float v0 = acc[mt][nt][half * 2];
                float v1 = acc[mt][nt][half * 2 + 1];
                if (BIAS) { v0 += bias[col]; v1 += bias[col + 1]; }
                if (RES) {
                    const float2 r2 = *reinterpret_cast<const float2*>(
                        &res[(size_t)row * N + col]);
                    v0 += r2.x; v1 += r2.y;
                }
                if (RESH) {
                    const __half2 rh = *reinterpret_cast<const __half2*>(
                        &resh[(size_t)row * N + col]);
                    v0 += __half2float(rh.x); v1 += __half2float(rh.y);
                }
                if (RELU) { v0 = fmaxf(v0, 0.f); v1 = fmaxf(v1, 0.f); }
                const size_t o = (size_t)row * N + col;
                if (OUTF) {
                    float2 w = {v0, v1};
                    *reinterpret_cast<float2*>(&Cf[o]) = w;
                }
                if (OUTH)
                    *reinterpret_cast<__half2*>(&Ch[o]) = __floats2half2_rn(v0, v1);
            }
        }
    }
}

// ---------------------------------------------------------------------------
// fp16 mma flash attention, causal (R13 body, LPT dispatch).
// NEW: pinned 2 CTAs/SM; score scale folded into softmax FMA (no scale pass).
// ---------------------------------------------------------------------------
#define AQH 0
#define AKVB 18432
#define ATTN_SMEM (18432 + 3 * 18432)   // 73728

__global__ __launch_bounds__(256, 2) void attn_mma(
    const __half* __restrict__ qkv, __half* __restrict__ yh)
{
    extern __shared__ char smem[];
    const uint32_t sb = smem_u32(smem);
    const int tid = threadIdx.x, lane = tid & 31, w = tid >> 5;
    const int bhh = blockIdx.y, b = bhh >> 4, h = bhh & 15;
    const int xi = gridDim.x - 1 - blockIdx.x;   // LPT: heavy CTAs first
    const int t0 = xi * 128;
    const int last = 2 * xi + 1;                 // >= 1 always
    const size_t rbase = ((size_t)b * TT) * 3072 + h * 64;
    const float SC2 = 0.045084220027780106f;     // scale * log2(e)

    // Q load: group 0
    {
        const int qr = tid >> 1;
        const int sg = (tid & 1) * 4;
#pragma unroll
        for (int j = 0; j < 4; j++) {
            size_t g = rbase + (size_t)(t0 + qr) * 3072 + (sg + j) * 8;
            uint32_t so = (uint32_t)qr * 144 + (sg + j) * 16;
            cp_async16(sb + AQH + so, qkv + g);
        }
    }
    CP_COMMIT();

    const int kr = tid >> 2;
    const int ksg = (tid & 3) * 2;
    auto issueKV = [&](int it) {
        const int s0 = it * 64;
        const uint32_t pb = AKVB + (uint32_t)(it % 3) * 18432;
#pragma unroll
        for (int j = 0; j < 2; j++) {
            size_t gk = rbase + 1024 + (size_t)(s0 + kr) * 3072 + (ksg + j) * 8;
            uint32_t so = (uint32_t)kr * 144 + (ksg + j) * 16;
            cp_async16(sb + pb + so, qkv + gk);               // K
            cp_async16(sb + pb + 9216 + so, qkv + gk + 1024); // V
        }
        CP_COMMIT();
    };

    issueKV(0);
    issueKV(1);
    CP_WAIT(2);
    __syncthreads();

    const int t8 = lane >> 3, r8 = lane & 7;
    const int aR = r8 + ((t8 & 1) << 3);
    const int aK = (t8 & 2) << 2;
    const int bR = r8 + ((t8 >> 1) << 3);
    const int bK = (t8 & 1) << 3;

    uint32_t qf[4][4];
#pragma unroll
    for (int kd = 0; kd < 4; kd++)
        ldsm_x4(qf[kd], sb + AQH + (uint32_t)(w * 16 + aR) * 144 + (kd * 16 + aK) * 2);

    // m kept in SCALED (exp2) domain; raw-score maxima converted via SC2.
    float m[2] = {-1e30f, -1e30f}, l[2] = {0.f, 0.f};
    float O[8][4];
#pragma unroll
    for (int i = 0; i < 8; i++)
#pragma unroll
        for (int j = 0; j < 4; j++) O[i][j] = 0.f;

    const int qr0 = w * 16 + (lane >> 2);

    for (int it = 0; it <= last; it++) {
        if (it < last) { CP_WAIT(1); } else { CP_WAIT(0); }
        __syncthreads();
        if (it + 2 <= last) issueKV(it + 2);

        const uint32_t pb = AKVB + (uint32_t)(it % 3) * 18432;
        const int s0 = it * 64;

        float s[8][4];
#pragma unroll
        for (int i = 0; i < 8; i++)
#pragma unroll
            for (int j = 0; j < 4; j++) s[i][j] = 0.f;

#pragma unroll
        for (int kd = 0; kd < 4; kd++) {
            uint32_t kb[4][4];
#pragma unroll
            for (int g = 0; g < 4; g++)
                ldsm_x4(kb[g], sb + pb +
                        (uint32_t)(g * 16 + bR) * 144 + (kd * 16 + bK) * 2);
#pragma unroll
            for (int g = 0; g < 4; g++) {
                mma_f16(s[2 * g],     qf[kd], &kb[g][0]);
                mma_f16(s[2 * g + 1], qf[kd], &kb[g][2]);
            }
        }

        // Causal mask in RAW score domain (SC2 > 0 preserves ordering)
        if (it >= last - 1) {
#pragma unroll
            for (int nt = 0; nt < 8; nt++)
#pragma unroll
                for (int e = 0; e < 4; e++) {
                    int kc = s0 + nt * 8 + (lane & 3) * 2 + (e & 1);
                    int qr = t0 + qr0 + (e >> 1) * 8;
                    if (kc > qr) s[nt][e] = -1e30f;
                }
        }

        // Row max over RAW scores, then convert to scaled domain
        float mnr[2] = {-1e30f, -1e30f};
#pragma unroll
        for (int nt = 0; nt < 8; nt++) {
            mnr[0] = fmaxf(mnr[0], fmaxf(s[nt][0], s[nt][1]));
            mnr[1] = fmaxf(mnr[1], fmaxf(s[nt][2], s[nt][3]));
        }
#pragma unroll
        for (int i = 0; i < 2; i++) {
            mnr[i] = fmaxf(mnr[i], __shfl_xor_sync(0xffffffffu, mnr[i], 1));
            mnr[i] = fmaxf(mnr[i], __shfl_xor_sync(0xffffffffu, mnr[i], 2));
        }
        float alpha[2];
#pragma unroll
        for (int i = 0; i < 2; i++) {
            float mn = fmaxf(m[i], mnr[i] * SC2);   // scaled-domain new max
            alpha[i] = fast_exp2(m[i] - mn);
            m[i] = mn;
        }
        // p = exp2(s*SC2 - m): single FMA + EX2 per element
        float rs[2] = {0.f, 0.f};
#pragma unroll
        for (int nt = 0; nt < 8; nt++) {
#pragma unroll
            for (int e = 0; e < 4; e++) {
                float p = fast_exp2(fmaf(s[nt][e], SC2, -m[e >> 1]));
                s[nt][e] = p;
                rs[e >> 1] += p;
            }
        }
#pragma unroll
        for (int i = 0; i < 2; i++) {
            rs[i] += __shfl_xor_sync(0xffffffffu, rs[i], 1);
            rs[i] += __shfl_xor_sync(0xffffffffu, rs[i], 2);
            l[i] = l[i] * alpha[i] + rs[i];
        }
#pragma unroll
        for (int nt = 0; nt < 8; nt++) {
            O[nt][0] *= alpha[0]; O[nt][1] *= alpha[0];
            O[nt][2] *= alpha[1]; O[nt][3] *= alpha[1];
        }

#pragma unroll
        for (int kk = 0; kk < 4; kk++) {
            uint32_t pa[4];
            pa[0] = pack_h2(s[2 * kk][0],     s[2 * kk][1]);
            pa[1] = pack_h2(s[2 * kk][2],     s[2 * kk][3]);
            pa[2] = pack_h2(s[2 * kk + 1][0], s[2 * kk + 1][1]);
            pa[3] = pack_h2(s[2 * kk + 1][2], s[2 * kk + 1][3]);
#pragma unroll
            for (int dg = 0; dg < 4; dg++) {
                uint32_t vb[4];
                ldsm_x4_t(vb, sb + pb + 9216 +
                          (uint32_t)(kk * 16 + aR) * 144 + (dg * 16 + aK) * 2);
                mma_f16(O[dg * 2],     pa, &vb[0]);
                mma_f16(O[dg * 2 + 1], pa, &vb[2]);
            }
        }
    }

    float inv[2] = {1.0f / l[0], 1.0f / l[1]};
    const size_t ob = ((size_t)b * TT) * CC + h * 64;
#pragma unroll
    for (int nt = 0; nt < 8; nt++) {
        int col = nt * 8 + (lane & 3) * 2;
#pragma unroll
        for (int i = 0; i < 2; i++) {
            int row = t0 + qr0 + i * 8;
            size_t o = ob + (size_t)row * CC + col;
            *reinterpret_cast<__half2*>(&yh[o]) =
                __floats2half2_rn(O[nt][2 * i] * inv[i], O[nt][2 * i + 1] * inv[i]);
        }
    }
}

// ---------------------------------------------------------------------------
// Launch sequence
// ---------------------------------------------------------------------------
extern "C" void kernel_launch(void* const* d_in, const int* in_sizes, int n_in,
                              void* d_out, int out_size)
{
    const float* x     = (const float*)d_in[0];
    const float* Wq    = (const float*)d_in[1];
    const float* Wk    = (const float*)d_in[2];
    const float* Wv    = (const float*)d_in[3];
    const float* Wproj = (const float*)d_in[4];
    const float* bproj = (const float*)d_in[5];
    const float* W1    = (const float*)d_in[6];
    const float* b1    = (const float*)d_in[7];
    const float* W2    = (const float*)d_in[8];
    const float* b2    = (const float*)d_in[9];
    float* out = (float*)d_out;

    __half *xh, *Bqkv, *Bp, *B1, *B2, *qkv, *yh, *x2h, *h1h;
    cudaGetSymbolAddress((void**)&xh,  g_xh);
    cudaGetSymbolAddress((void**)&Bqkv, g_Bqkv);
    cudaGetSymbolAddress((void**)&Bp,  g_Bp);
    cudaGetSymbolAddress((void**)&B1,  g_B1);   cudaGetSymbolAddress((void**)&B2, g_B2);
    cudaGetSymbolAddress((void**)&qkv, g_qkv);
    cudaGetSymbolAddress((void**)&yh,  g_yh);
    cudaGetSymbolAddress((void**)&x2h, g_x2h);
    cudaGetSymbolAddress((void**)&h1h, g_h1h);

    cudaFuncSetAttribute(gemm_mma<false,false,false,false,false,true>,
                         cudaFuncAttributeMaxDynamicSharedMemorySize, GEMM_SMEM);
    cudaFuncSetAttribute(gemm_mma<true,false,true,false,false,true>,
                         cudaFuncAttributeMaxDynamicSharedMemorySize, GEMM_SMEM);
    cudaFuncSetAttribute(gemm_mma<true,true,false,false,false,true>,
                         cudaFuncAttributeMaxDynamicSharedMemorySize, GEMM_SMEM);
    cudaFuncSetAttribute(gemm_mma<true,false,false,true,true,false>,
                         cudaFuncAttributeMaxDynamicSharedMemorySize, GEMM_SMEM);
    cudaFuncSetAttribute(attn_mma,
                         cudaFuncAttributeMaxDynamicSharedMemorySize, ATTN_SMEM);

    dim3 tpb(256);

    // Fused prepass
    prepass_all<<<20480, tpb>>>(x, xh, Wq, Wk, Wv, Wproj, W1, W2,
                                Bqkv, Bp, B1, B2);

    // Fused QKV -> qkv fp16
    gemm_mma<false,false,false,false,false,true>
        <<<dim3(3072 / 128, MROWS / 128), tpb, GEMM_SMEM>>>(
        xh, Bqkv, nullptr, nullptr, nullptr, nullptr, qkv, MROWS, 3072, CC);

    // Causal attention -> y fp16 (LPT order)
    attn_mma<<<dim3(TT / 128, BB * 16), tpb, ATTN_SMEM>>>(qkv, yh);

    // Output projection + bias + residual(x fp32) -> x2h fp16
    gemm_mma<true,false,true,false,false,true>
        <<<dim3(CC / 128, MROWS / 128), tpb, GEMM_SMEM>>>(
        yh, Bp, bproj, x, nullptr, nullptr, x2h, MROWS, CC, CC);

    // FF1: relu(x2 @ W1 + b1) -> h1 fp16
    gemm_mma<true,true,false,false,false,true>
        <<<dim3(FF / 128, MROWS / 128), tpb, GEMM_SMEM>>>(
        x2h, B1, b1, nullptr, nullptr, nullptr, h1h, MROWS, FF, CC);

    // FF2: h1 @ W2 + b2 + x2h (fp16 residual) -> out fp32
    gemm_mma<true,false,false,true,true,false>
        <<<dim3(CC / 128, MROWS / 128), tpb, GEMM_SMEM>>>(
        h1h, B2, b2, nullptr, x2h, out, nullptr, MROWS, CC, FF);
}